// round 3
// baseline (speedup 1.0000x reference)
#include <cuda_runtime.h>
#include <math.h>

#define NXS 8192
#define DXS 8
#define HS  1024

// ---------------- scratch (allocation-free: __device__ globals) -------------
__device__ float g_z1[NXS * HS];   // tanh(x W1^T + b1)
__device__ float g_z2[NXS * HS];   // tanh(z1 W2^T + b2)
__device__ float g_t [NXS * HS];   // u @ W2, u = W3*(1-z2^2)

// ---------------- packed f32x2 helpers (FFMA2 — ptxas won't emit this) ------
__device__ __forceinline__ unsigned long long pk2(float a) {
    unsigned long long r;
    asm("mov.b64 %0, {%1, %2};" : "=l"(r) : "f"(a), "f"(a));
    return r;
}
__device__ __forceinline__ void fma2(unsigned long long& c,
                                     unsigned long long a,
                                     unsigned long long b) {
    asm("fma.rn.f32x2 %0, %1, %2, %0;" : "+l"(c) : "l"(a), "l"(b));
}
__device__ __forceinline__ void unpk(unsigned long long v, float& lo, float& hi) {
    asm("mov.b64 {%0, %1}, %2;" : "=f"(lo), "=f"(hi) : "l"(v));
}

// ---------------- layer 1: z1 = tanh(x @ W1^T + b1) -------------------------
__global__ void k_layer1(const float* __restrict__ x,
                         const float* __restrict__ W1,
                         const float* __restrict__ b1) {
    __shared__ float xs[DXS];
    int n = blockIdx.x;
    if (threadIdx.x < DXS) xs[threadIdx.x] = x[n * DXS + threadIdx.x];
    __syncthreads();
#pragma unroll
    for (int jj = 0; jj < HS / 256; jj++) {
        int j = jj * 256 + threadIdx.x;
        const float4* w = reinterpret_cast<const float4*>(&W1[j * DXS]);
        float4 w0 = w[0], w1 = w[1];
        float acc = b1[j]
            + xs[0] * w0.x + xs[1] * w0.y + xs[2] * w0.z + xs[3] * w0.w
            + xs[4] * w1.x + xs[5] * w1.y + xs[6] * w1.z + xs[7] * w1.w;
        g_z1[(size_t)n * HS + j] = tanhf(acc);
    }
}

// ---------------- GEMM: 128x128x16 tiles, 8x8 microtile, FFMA2 inner loop ---
// MODE 0:  g_z2 = tanh(g_z1 @ W2^T + b2)    (B = W2 [N,K] row-major -> transpose)
// MODE 1:  g_t  = (W3*(1-g_z2^2)) @ W2      (B = W2 [K,N] row-major -> direct)
template <int MODE>
__global__ __launch_bounds__(256)
void gemm_kernel(const float* __restrict__ B,
                 const float* __restrict__ aux) { // MODE0: b2, MODE1: W3
    const int Kd = HS, Nd = HS;
    const int BM = 128, BN = 128, BK = 16, PAD = 4;
    __shared__ __align__(16) float As[BK][BM + PAD];
    __shared__ __align__(16) float Bs[BK][BN + PAD];

    const float* __restrict__ A = (MODE == 0) ? g_z1 : g_z2;
    float* __restrict__ C       = (MODE == 0) ? g_z2 : g_t;

    const int tid = threadIdx.x;
    const int tx = tid & 15, ty = tid >> 4;
    const int bM = blockIdx.y * BM, bN = blockIdx.x * BN;

    unsigned long long acc[8][4];
#pragma unroll
    for (int i = 0; i < 8; i++)
#pragma unroll
        for (int j = 0; j < 4; j++) acc[i][j] = 0ull;

    auto gload = [&](int kt, float4(&a)[2], float4(&b)[2]) {
#pragma unroll
        for (int r = 0; r < 2; r++) {
            int idx = tid + r * 256;
            int m = idx >> 2, k4 = (idx & 3) << 2;
            float4 v = *reinterpret_cast<const float4*>(&A[(size_t)(bM + m) * Kd + kt + k4]);
            if (MODE == 1) {
                float4 w = *reinterpret_cast<const float4*>(&aux[kt + k4]);
                v.x = w.x * (1.0f - v.x * v.x);
                v.y = w.y * (1.0f - v.y * v.y);
                v.z = w.z * (1.0f - v.z * v.z);
                v.w = w.w * (1.0f - v.w * v.w);
            }
            a[r] = v;
            if (MODE == 0) {
                b[r] = *reinterpret_cast<const float4*>(&B[(size_t)(bN + m) * Kd + kt + k4]);
            } else {
                int k = idx >> 5, n4 = (idx & 31) << 2;
                b[r] = *reinterpret_cast<const float4*>(&B[(size_t)(kt + k) * Nd + bN + n4]);
            }
        }
    };
    auto sstore = [&](float4(&a)[2], float4(&b)[2]) {
#pragma unroll
        for (int r = 0; r < 2; r++) {
            int idx = tid + r * 256;
            int m = idx >> 2, k4 = (idx & 3) << 2;
            As[k4 + 0][m] = a[r].x; As[k4 + 1][m] = a[r].y;
            As[k4 + 2][m] = a[r].z; As[k4 + 3][m] = a[r].w;
            if (MODE == 0) {
                Bs[k4 + 0][m] = b[r].x; Bs[k4 + 1][m] = b[r].y;
                Bs[k4 + 2][m] = b[r].z; Bs[k4 + 3][m] = b[r].w;
            } else {
                int k = idx >> 5, n4 = (idx & 31) << 2;
                *reinterpret_cast<float4*>(&Bs[k][n4]) = b[r];
            }
        }
    };

    float4 av[2], bv[2], avn[2], bvn[2];
    gload(0, av, bv);

    for (int kt = 0; kt < Kd; kt += BK) {
        sstore(av, bv);
        __syncthreads();
        int ktn = kt + BK;
        if (ktn < Kd) gload(ktn, avn, bvn);

#pragma unroll
        for (int k = 0; k < BK; k++) {
            float4 a0 = *reinterpret_cast<const float4*>(&As[k][ty * 8]);
            float4 a1 = *reinterpret_cast<const float4*>(&As[k][ty * 8 + 4]);
            ulonglong2 bA = *reinterpret_cast<const ulonglong2*>(&Bs[k][tx * 8]);
            ulonglong2 bB = *reinterpret_cast<const ulonglong2*>(&Bs[k][tx * 8 + 4]);
            unsigned long long bb0 = bA.x, bb1 = bA.y, bb2 = bB.x, bb3 = bB.y;
            float af[8] = {a0.x, a0.y, a0.z, a0.w, a1.x, a1.y, a1.z, a1.w};
#pragma unroll
            for (int i = 0; i < 8; i++) {
                unsigned long long aa = pk2(af[i]);
                fma2(acc[i][0], aa, bb0);
                fma2(acc[i][1], aa, bb1);
                fma2(acc[i][2], aa, bb2);
                fma2(acc[i][3], aa, bb3);
            }
        }
        __syncthreads();
        if (ktn < Kd) {
#pragma unroll
            for (int r = 0; r < 2; r++) { av[r] = avn[r]; bv[r] = bvn[r]; }
        }
    }

    // epilogue
    float bcol[8];
    if (MODE == 0) {
        float4 t0 = *reinterpret_cast<const float4*>(&aux[bN + tx * 8]);
        float4 t1 = *reinterpret_cast<const float4*>(&aux[bN + tx * 8 + 4]);
        bcol[0] = t0.x; bcol[1] = t0.y; bcol[2] = t0.z; bcol[3] = t0.w;
        bcol[4] = t1.x; bcol[5] = t1.y; bcol[6] = t1.z; bcol[7] = t1.w;
    }
#pragma unroll
    for (int i = 0; i < 8; i++) {
        float c[8];
#pragma unroll
        for (int j2 = 0; j2 < 4; j2++) unpk(acc[i][j2], c[2 * j2], c[2 * j2 + 1]);
        if (MODE == 0) {
#pragma unroll
            for (int j = 0; j < 8; j++) c[j] = tanhf(c[j] + bcol[j]);
        }
        size_t row = (size_t)(bM + ty * 8 + i);
        float4* dst = reinterpret_cast<float4*>(&C[row * Nd + bN + tx * 8]);
        dst[0] = make_float4(c[0], c[1], c[2], c[3]);
        dst[1] = make_float4(c[4], c[5], c[6], c[7]);
    }
}

// ---------------- y = z2 @ W3^T + b3  (one warp per row) --------------------
__global__ void k_y(const float* __restrict__ W3,
                    const float* __restrict__ b3,
                    float* __restrict__ y) {
    int warp = threadIdx.x >> 5, lane = threadIdx.x & 31;
    int n = blockIdx.x * 8 + warp;
    const float4* z = reinterpret_cast<const float4*>(&g_z2[(size_t)n * HS]);
    const float4* w = reinterpret_cast<const float4*>(W3);
    float acc = 0.0f;
#pragma unroll
    for (int it = 0; it < HS / 128; it++) {
        int i = it * 32 + lane;
        float4 zv = z[i], wv = w[i];
        acc += zv.x * wv.x + zv.y * wv.y + zv.z * wv.z + zv.w * wv.w;
    }
#pragma unroll
    for (int off = 16; off > 0; off >>= 1)
        acc += __shfl_xor_sync(0xffffffffu, acc, off);
    if (lane == 0) y[n] = acc + b3[0];
}

// ------- dydx[k,n] = sum_j (t[n,j]*(1-z1[n,j]^2)) * W1[j,k]  (warp per row) --
__global__ void k_dydx(const float* __restrict__ W1,
                       float* __restrict__ dydx) {
    int warp = threadIdx.x >> 5, lane = threadIdx.x & 31;
    int n = blockIdx.x * 8 + warp;
    const float4* tp = reinterpret_cast<const float4*>(&g_t [(size_t)n * HS]);
    const float4* zp = reinterpret_cast<const float4*>(&g_z1[(size_t)n * HS]);
    float acc[8];
#pragma unroll
    for (int k = 0; k < 8; k++) acc[k] = 0.0f;
#pragma unroll
    for (int it = 0; it < HS / 128; it++) {
        int i = it * 32 + lane;
        float4 tv = tp[i], zv = zp[i];
        float s[4] = { tv.x * (1.0f - zv.x * zv.x), tv.y * (1.0f - zv.y * zv.y),
                       tv.z * (1.0f - zv.z * zv.z), tv.w * (1.0f - zv.w * zv.w) };
#pragma unroll
        for (int e = 0; e < 4; e++) {
            int j = i * 4 + e;
            const float4* w = reinterpret_cast<const float4*>(&W1[j * DXS]);
            float4 w0 = w[0], w1 = w[1];
            acc[0] += s[e] * w0.x; acc[1] += s[e] * w0.y;
            acc[2] += s[e] * w0.z; acc[3] += s[e] * w0.w;
            acc[4] += s[e] * w1.x; acc[5] += s[e] * w1.y;
            acc[6] += s[e] * w1.z; acc[7] += s[e] * w1.w;
        }
    }
#pragma unroll
    for (int k = 0; k < 8; k++)
#pragma unroll
        for (int off = 16; off > 0; off >>= 1)
            acc[k] += __shfl_xor_sync(0xffffffffu, acc[k], off);
    if (lane == 0) {
#pragma unroll
        for (int k = 0; k < 8; k++) dydx[(size_t)k * NXS + n] = acc[k];
    }
}

// ---------------- launch -----------------------------------------------------
extern "C" void kernel_launch(void* const* d_in, const int* in_sizes, int n_in,
                              void* d_out, int out_size) {
    const float* x  = (const float*)d_in[0];
    const float* W1 = (const float*)d_in[1];
    const float* b1 = (const float*)d_in[2];
    const float* W2 = (const float*)d_in[3];
    const float* b2 = (const float*)d_in[4];
    const float* W3 = (const float*)d_in[5];
    const float* b3 = (const float*)d_in[6];
    float* out = (float*)d_out;

    k_layer1<<<NXS, 256>>>(x, W1, b1);

    dim3 grid(HS / 128, NXS / 128);
    gemm_kernel<0><<<grid, 256>>>(W2, b2);   // z2 = tanh(z1 W2^T + b2)
    gemm_kernel<1><<<grid, 256>>>(W2, W3);   // t  = (W3*(1-z2^2)) @ W2

    k_y<<<NXS / 8, 256>>>(W3, b3, out);              // y -> out[0 : NX)
    k_dydx<<<NXS / 8, 256>>>(W1, out + NXS);         // dydx -> out[NX : NX + DX*NX)
}